// round 7
// baseline (speedup 1.0000x reference)
#include <cuda_runtime.h>

typedef unsigned long long ULL;

#define BB 256
#define TT 1024
#define FF 64
#define UU 128
#define G3 384   // 3*U

// ---------------- scratch buffers (no cudaMalloc allowed) ----------------
static __device__ float g_xw1[(size_t)BB * TT * G3];   // input proj layer1 [B,T,384]
static __device__ float g_seq1[(size_t)BB * TT * UU];  // layer1 hidden seq [B,T,128]
static __device__ float g_xw2[(size_t)BB * TT * G3];   // input proj layer2 [B,T,384]

// ---------------- helpers ----------------
__device__ __forceinline__ ULL fma2(ULL a, ULL b, ULL c) {
    ULL d;
    asm("fma.rn.f32x2 %0, %1, %2, %3;" : "=l"(d) : "l"(a), "l"(b), "l"(c));
    return d;
}
__device__ __forceinline__ ULL addp(ULL a, ULL b) {
    ULL d;
    asm("add.rn.f32x2 %0, %1, %2;" : "=l"(d) : "l"(a), "l"(b));
    return d;
}
__device__ __forceinline__ ULL pack2(float lo, float hi) {
    ULL d;
    asm("mov.b64 %0, {%1, %2};" : "=l"(d) : "f"(lo), "f"(hi));
    return d;
}
__device__ __forceinline__ float2 unpack2(ULL v) {
    float lo, hi;
    asm("mov.b64 {%0, %1}, %2;" : "=f"(lo), "=f"(hi) : "l"(v));
    return make_float2(lo, hi);
}
__device__ __forceinline__ float4 add4(float4 a, float4 b) {
    return make_float4(a.x + b.x, a.y + b.y, a.z + b.z, a.w + b.w);
}
__device__ __forceinline__ float sigm(float x) {
    return 1.0f / (1.0f + __expf(-x));
}

// =====================================================================
// GEMM: out[M,384] = X[M,K] @ W[K,384] + bias,  K = 4*KC (64 or 128)
// (unchanged — at its fp32 fma floor ~510us combined)
// =====================================================================
template <int KC>
__global__ void __launch_bounds__(384, 1) gemm_kernel(
    const float* __restrict__ X, const float* __restrict__ W,
    const float* __restrict__ bias, float* __restrict__ out, int nblk)
{
    constexpr int K = 4 * KC;
    extern __shared__ char smem[];
    ulonglong2* Ws2   = (ulonglong2*)smem;
    float4*     Wf4   = (float4*)smem;
    ulonglong2* part2 = (ulonglong2*)(smem + (size_t)K * 1536);
    float4*     partf = (float4*)(smem + (size_t)K * 1536);
    ULL*        xp    = (ULL*)(smem + (size_t)K * 1536 + 24576);
    float2*     xpf   = (float2*)xp;

    const int t  = threadIdx.x;
    const int cq = t % 96;
    const int kg = t / 96;
    const int kbase = kg * KC;

    for (int i = t; i < K * 96; i += 384) Wf4[i] = ((const float4*)W)[i];
    float4 bq = ((const float4*)bias)[cq];
    ULL b01 = pack2(bq.x, bq.y), b23 = pack2(bq.z, bq.w);
    __syncthreads();

    for (int blk = blockIdx.x; blk < nblk; blk += gridDim.x) {
        const int row0 = blk * 4;
        for (int i = t; i < 4 * K; i += 384) {
            float v = X[(size_t)row0 * K + i];
            xpf[i] = make_float2(v, v);
        }
        __syncthreads();

        ULL a0[4], a1[4];
#pragma unroll
        for (int r = 0; r < 4; r++) {
            a0[r] = (kg == 0) ? b01 : 0ull;
            a1[r] = (kg == 0) ? b23 : 0ull;
        }
        const ulonglong2* Up = Ws2 + kbase * 96 + cq;
        const ULL* x0 = xp + kbase;
#pragma unroll
        for (int kk = 0; kk < KC; kk++) {
            ulonglong2 u = Up[kk * 96];
            ULL h;
            h = x0[kk];           a0[0] = fma2(u.x, h, a0[0]); a1[0] = fma2(u.y, h, a1[0]);
            h = x0[K + kk];       a0[1] = fma2(u.x, h, a0[1]); a1[1] = fma2(u.y, h, a1[1]);
            h = x0[2 * K + kk];   a0[2] = fma2(u.x, h, a0[2]); a1[2] = fma2(u.y, h, a1[2]);
            h = x0[3 * K + kk];   a0[3] = fma2(u.x, h, a0[3]); a1[3] = fma2(u.y, h, a1[3]);
        }
        ulonglong2* P = part2 + kg * 4 * 96 + cq;
#pragma unroll
        for (int r = 0; r < 4; r++) P[r * 96] = make_ulonglong2(a0[r], a1[r]);
        __syncthreads();

        {
            float4 s = partf[kg * 96 + cq];
#pragma unroll
            for (int kg2 = 1; kg2 < 4; kg2++)
                s = add4(s, partf[(kg2 * 4 + kg) * 96 + cq]);
            ((float4*)out)[(size_t)(row0 + kg) * 96 + cq] = s;
        }
        __syncthreads();
    }
}

// =====================================================================
// GRU scan v5: one (gate, column) per thread; U fully register-resident;
// no k-split, no reduction. 128 CTAs x 2 rows, 384 threads.
//   thread t: g = t>>7 (gate z/r/h), c = t&127 (output column)
//   regs: Ur[64] = packed pairs (U[2m][g*128+c], U[2m+1][g*128+c])
//   mainloop: 32 x { 2 broadcast LDS.128 of h (warp-uniform, conflict-free),
//                    4 fma2 } -> complete column dot product per thread
//   partials: part[g][c] float2 (rows), 1 STS; barrier;
//   gate tail: t<128, h_old in regs; 2 barriers/step total.
// =====================================================================
__global__ void __launch_bounds__(384, 1) scan_kernel(
    const float* __restrict__ xw,       // [B,T,384]
    const float* __restrict__ Urec,     // [128,384]
    const float* __restrict__ rbias,    // [384]
    float* __restrict__ seqout,         // [B,T,128] or null
    float* __restrict__ hfin1,          // [B,128]
    float* __restrict__ hfin2)          // optional second copy or null
{
    __shared__ alignas(16) float hbuf[2][2][UU];   // [buf][row][c]
    __shared__ float2 part[3][UU];                 // [gate][c] -> (row0,row1)

    const int t = threadIdx.x;
    const int g = t >> 7;       // 0..2
    const int c = t & 127;
    const int row0 = blockIdx.x * 2;

    // load this thread's full U column (k=0..127) as 64 packed f32x2 regs
    ULL Ur[64];
#pragma unroll
    for (int m = 0; m < 64; m++) {
        float u0 = Urec[(size_t)(2 * m) * G3 + g * 128 + c];
        float u1 = Urec[(size_t)(2 * m + 1) * G3 + g * 128 + c];
        Ur[m] = pack2(u0, u1);
    }
    const float bias = rbias[g * 128 + c];

    if (t < 256) hbuf[0][t >> 7][t & 127] = 0.0f;
    float hprev0 = 0.0f, hprev1 = 0.0f;       // live only in t<128
    __syncthreads();

    for (int step = 0; step < TT; ++step) {
        const int rb = step & 1;

        // prefetch xw for the gate phase (t<128); overlapped with mainloop
        float xz0, xz1, xr0, xr1, xh0, xh1;
        if (t < 128) {
            const float* p0 = xw + ((size_t)(row0 + 0) * TT + step) * G3 + c;
            const float* p1 = xw + ((size_t)(row0 + 1) * TT + step) * G3 + c;
            xz0 = p0[0]; xr0 = p0[128]; xh0 = p0[256];
            xz1 = p1[0]; xr1 = p1[128]; xh1 = p1[256];
        }

        const ulonglong2* h0 = (const ulonglong2*)hbuf[rb][0];  // warp-uniform
        const ulonglong2* h1 = (const ulonglong2*)hbuf[rb][1];
        ULL aE0 = 0, aO0 = 0, aE1 = 0, aO1 = 0;
#pragma unroll
        for (int j = 0; j < 32; j++) {
            ulonglong2 ha = h0[j];    // broadcast: (h[4j],h[4j+1]),(h[4j+2],h[4j+3])
            ulonglong2 hb = h1[j];
            aE0 = fma2(Ur[2 * j],     ha.x, aE0);
            aO0 = fma2(Ur[2 * j + 1], ha.y, aO0);
            aE1 = fma2(Ur[2 * j],     hb.x, aE1);
            aO1 = fma2(Ur[2 * j + 1], hb.y, aO1);
        }
        float2 s0 = unpack2(addp(aE0, aO0));
        float2 s1 = unpack2(addp(aE1, aO1));
        part[g][c] = make_float2(s0.x + s0.y + bias, s1.x + s1.y + bias);
        __syncthreads();

        if (t < 128) {
            float2 pz = part[0][c], pr = part[1][c], ph = part[2][c];
            float z0 = sigm(xz0 + pz.x);
            float z1 = sigm(xz1 + pz.y);
            float r0 = sigm(xr0 + pr.x);
            float r1 = sigm(xr1 + pr.y);
            float hh0 = fmaxf(xh0 + r0 * ph.x, 0.0f);
            float hh1 = fmaxf(xh1 + r1 * ph.y, 0.0f);
            hprev0 = z0 * hprev0 + (1.0f - z0) * hh0;
            hprev1 = z1 * hprev1 + (1.0f - z1) * hh1;
            hbuf[rb ^ 1][0][c] = hprev0;
            hbuf[rb ^ 1][1][c] = hprev1;
            if (seqout) {
                seqout[((size_t)(row0 + 0) * TT + step) * UU + c] = hprev0;
                seqout[((size_t)(row0 + 1) * TT + step) * UU + c] = hprev1;
            }
        }
        __syncthreads();
    }

    if (t < 128) {
        hfin1[(size_t)(row0 + 0) * UU + c] = hprev0;
        hfin1[(size_t)(row0 + 1) * UU + c] = hprev1;
        if (hfin2) {
            hfin2[(size_t)(row0 + 0) * UU + c] = hprev0;
            hfin2[(size_t)(row0 + 1) * UU + c] = hprev1;
        }
    }
}

// =====================================================================
// launch
// =====================================================================
extern "C" void kernel_launch(void* const* d_in, const int* in_sizes, int n_in,
                              void* d_out, int out_size)
{
    (void)in_sizes; (void)n_in; (void)out_size;
    const float* input = (const float*)d_in[0];  // [256,1024,64]
    const float* W1    = (const float*)d_in[1];  // [64,384]
    const float* U1    = (const float*)d_in[2];  // [128,384]
    const float* b1    = (const float*)d_in[3];  // [2,384]
    const float* W2    = (const float*)d_in[4];  // [128,384]
    const float* U2    = (const float*)d_in[5];  // [128,384]
    const float* b2    = (const float*)d_in[6];  // [2,384]
    float* out = (float*)d_out;                  // [3*256*128]: x | state1 | state2

    float *xw1, *seq1, *xw2;
    cudaGetSymbolAddress((void**)&xw1,  g_xw1);
    cudaGetSymbolAddress((void**)&seq1, g_seq1);
    cudaGetSymbolAddress((void**)&xw2,  g_xw2);

    const int SMEM_G1 = 64 * 1536 + 24576 + 2048;    // 124928
    const int SMEM_G2 = 128 * 1536 + 24576 + 4096;   // 225280

    cudaFuncSetAttribute(gemm_kernel<16>, cudaFuncAttributeMaxDynamicSharedMemorySize, SMEM_G1);
    cudaFuncSetAttribute(gemm_kernel<32>, cudaFuncAttributeMaxDynamicSharedMemorySize, SMEM_G2);

    const int nblk = (BB * TT) / 4;  // 65536 row-blocks of 4

    // Layer 1 input projection: xw1 = input @ W1 + b1[0]
    gemm_kernel<16><<<148, 384, SMEM_G1>>>(input, W1, b1, xw1, nblk);
    // Layer 1 scan: seq1, state1
    scan_kernel<<<128, 384>>>(xw1, U1, b1 + G3,
                              seq1, out + 32768, nullptr);
    // Layer 2 input projection: xw2 = seq1 @ W2 + b2[0]
    gemm_kernel<32><<<148, 384, SMEM_G2>>>(seq1, W2, b2, xw2, nblk);
    // Layer 2 scan: x (== state2)
    scan_kernel<<<128, 384>>>(xw2, U2, b2 + G3,
                              nullptr, out, out + 65536);
}

// round 8
// speedup vs baseline: 1.3981x; 1.3981x over previous
#include <cuda_runtime.h>

typedef unsigned long long ULL;

#define BB 256
#define TT 1024
#define FF 64
#define UU 128
#define G3 384   // 3*U

// ---------------- scratch buffers (no cudaMalloc allowed) ----------------
static __device__ float g_xw1[(size_t)BB * TT * G3];   // input proj layer1 [B,T,384]
static __device__ float g_seq1[(size_t)BB * TT * UU];  // layer1 hidden seq [B,T,128]
static __device__ float g_xw2[(size_t)BB * TT * G3];   // input proj layer2 [B,T,384]

// ---------------- helpers ----------------
__device__ __forceinline__ ULL fma2(ULL a, ULL b, ULL c) {
    ULL d;
    asm("fma.rn.f32x2 %0, %1, %2, %3;" : "=l"(d) : "l"(a), "l"(b), "l"(c));
    return d;
}
__device__ __forceinline__ ULL pack2(float lo, float hi) {
    ULL d;
    asm("mov.b64 %0, {%1, %2};" : "=l"(d) : "f"(lo), "f"(hi));
    return d;
}
__device__ __forceinline__ float4 add4(float4 a, float4 b) {
    return make_float4(a.x + b.x, a.y + b.y, a.z + b.z, a.w + b.w);
}
__device__ __forceinline__ float sigm(float x) {
    return 1.0f / (1.0f + __expf(-x));
}

// =====================================================================
// GEMM: out[M,384] = X[M,K] @ W[K,384] + bias,  K = 4*KC (64 or 128)
// (unchanged this round; known-good. Overhaul queued for next round.)
// =====================================================================
template <int KC>
__global__ void __launch_bounds__(384, 1) gemm_kernel(
    const float* __restrict__ X, const float* __restrict__ W,
    const float* __restrict__ bias, float* __restrict__ out, int nblk)
{
    constexpr int K = 4 * KC;
    extern __shared__ char smem[];
    ulonglong2* Ws2   = (ulonglong2*)smem;
    float4*     Wf4   = (float4*)smem;
    ulonglong2* part2 = (ulonglong2*)(smem + (size_t)K * 1536);
    float4*     partf = (float4*)(smem + (size_t)K * 1536);
    ULL*        xp    = (ULL*)(smem + (size_t)K * 1536 + 24576);
    float2*     xpf   = (float2*)xp;

    const int t  = threadIdx.x;
    const int cq = t % 96;
    const int kg = t / 96;
    const int kbase = kg * KC;

    for (int i = t; i < K * 96; i += 384) Wf4[i] = ((const float4*)W)[i];
    float4 bq = ((const float4*)bias)[cq];
    ULL b01 = pack2(bq.x, bq.y), b23 = pack2(bq.z, bq.w);
    __syncthreads();

    for (int blk = blockIdx.x; blk < nblk; blk += gridDim.x) {
        const int row0 = blk * 4;
        for (int i = t; i < 4 * K; i += 384) {
            float v = X[(size_t)row0 * K + i];
            xpf[i] = make_float2(v, v);
        }
        __syncthreads();

        ULL a0[4], a1[4];
#pragma unroll
        for (int r = 0; r < 4; r++) {
            a0[r] = (kg == 0) ? b01 : 0ull;
            a1[r] = (kg == 0) ? b23 : 0ull;
        }
        const ulonglong2* Up = Ws2 + kbase * 96 + cq;
        const ULL* x0 = xp + kbase;
#pragma unroll
        for (int kk = 0; kk < KC; kk++) {
            ulonglong2 u = Up[kk * 96];
            ULL h;
            h = x0[kk];           a0[0] = fma2(u.x, h, a0[0]); a1[0] = fma2(u.y, h, a1[0]);
            h = x0[K + kk];       a0[1] = fma2(u.x, h, a0[1]); a1[1] = fma2(u.y, h, a1[1]);
            h = x0[2 * K + kk];   a0[2] = fma2(u.x, h, a0[2]); a1[2] = fma2(u.y, h, a1[2]);
            h = x0[3 * K + kk];   a0[3] = fma2(u.x, h, a0[3]); a1[3] = fma2(u.y, h, a1[3]);
        }
        ulonglong2* P = part2 + kg * 4 * 96 + cq;
#pragma unroll
        for (int r = 0; r < 4; r++) P[r * 96] = make_ulonglong2(a0[r], a1[r]);
        __syncthreads();

        {
            float4 s = partf[kg * 96 + cq];
#pragma unroll
            for (int kg2 = 1; kg2 < 4; kg2++)
                s = add4(s, partf[(kg2 * 4 + kg) * 96 + cq]);
            ((float4*)out)[(size_t)(row0 + kg) * 96 + cq] = s;
        }
        __syncthreads();
    }
}

// =====================================================================
// GRU scan v6: smem-U at the traffic floor + shfl-broadcast h.
// 128 CTAs x 2 rows, 768 threads: kg = t/96 (8 k-slices of 16),
// cq = t%96 (4 columns). Per step:
//   - each lane loads ONE h scalar (lane<16: row0 k=kbase+lane;
//     lane>=16: row1), then 16 iters of { LDS.128 U, 2 shfl.idx h,
//     2 pack, 4 fma2 }  -> U traffic = exact 1536-wavefront floor,
//     fma = exact MAC floor, h broadcasts on the shuffle pipe.
//   - partials [8][2][96] ulonglong2 via 2 STS.128; barrier;
//   - 256-thread gate tail (row,c), h_old in regs; barrier.
// =====================================================================
__global__ void __launch_bounds__(768, 1) scan_kernel(
    const float* __restrict__ xw,       // [B,T,384]
    const float* __restrict__ Urec,     // [128,384]
    const float* __restrict__ rbias,    // [384]
    float* __restrict__ seqout,         // [B,T,128] or null
    float* __restrict__ hfin1,          // [B,128]
    float* __restrict__ hfin2)          // optional second copy or null
{
    extern __shared__ char smem[];
    float4*     Us4   = (float4*)smem;                      // [128][96] 196608 B
    const ulonglong2* Us2 = (const ulonglong2*)smem;
    ulonglong2* part  = (ulonglong2*)(smem + 196608);       // [8][2][96] 24576 B
    const float* partF = (const float*)(smem + 196608);
    float*      hs    = (float*)(smem + 196608 + 24576);    // [2][128] 1024 B

    const int t    = threadIdx.x;
    const int lane = t & 31;
    const int cq   = t % 96;
    const int kg   = t / 96;            // 0..7
    const int kbase = kg * 16;
    const int row0 = blockIdx.x * 2;

    // gate-phase mapping (t < 256)
    const int r_g = t >> 7;             // row 0/1
    const int c_g = t & 127;            // column

    // load U into smem (row-major [k][384] -> [k][96] float4)
    for (int i = t; i < UU * 96; i += 768) Us4[i] = ((const float4*)Urec)[i];

    // bias seeds (kg==0 lanes carry the bias)
    float4 bq = ((const float4*)rbias)[cq];
    ULL b01 = (kg == 0) ? pack2(bq.x, bq.y) : 0ull;
    ULL b23 = (kg == 0) ? pack2(bq.z, bq.w) : 0ull;

    if (t < 256) hs[t] = 0.0f;          // hs[2][128] zero
    float hprev = 0.0f;                 // gate threads' own h(row,c)
    __syncthreads();

    const ulonglong2* Ubase = Us2 + (size_t)kbase * 96 + cq;
    const float* hsrc = hs + (lane >> 4) * UU + kbase + (lane & 15);

    for (int step = 0; step < TT; ++step) {
        // gate threads prefetch xw (consumed after mainloop -> latency hidden)
        float xz = 0.f, xr = 0.f, xh = 0.f;
        if (t < 256) {
            const float* p = xw + ((size_t)(row0 + r_g) * TT + step) * G3 + c_g;
            xz = p[0]; xr = p[128]; xh = p[256];
        }

        // each lane: one h scalar (row = lane>>4, k = kbase + (lane&15))
        float h_f = *hsrc;

        ULL a00 = b01, a01 = b23;       // row0, cols (4cq,4cq+1),(4cq+2,4cq+3)
        ULL a10 = b01, a11 = b23;       // row1
#pragma unroll
        for (int j = 0; j < 16; j++) {
            ulonglong2 u = Ubase[j * 96];
            float hA = __shfl_sync(0xffffffffu, h_f, j);       // row0, k=kbase+j
            float hB = __shfl_sync(0xffffffffu, h_f, 16 + j);  // row1
            ULL hA2 = pack2(hA, hA);
            ULL hB2 = pack2(hB, hB);
            a00 = fma2(u.x, hA2, a00);
            a01 = fma2(u.y, hA2, a01);
            a10 = fma2(u.x, hB2, a10);
            a11 = fma2(u.y, hB2, a11);
        }
        part[(kg * 2 + 0) * 96 + cq] = make_ulonglong2(a00, a01);
        part[(kg * 2 + 1) * 96 + cq] = make_ulonglong2(a10, a11);
        __syncthreads();

        if (t < 256) {
            // sum the 8 k-slice partials for gates z, r, h at (r_g, c_g)
            // partF index: ((kg*2 + r)*384) + gate*128 + c   (ulonglong2 row = 384 floats)
            const float* pb = partF + r_g * 384 + c_g;
            float az = 0.f, ar = 0.f, ah = 0.f;
#pragma unroll
            for (int k2 = 0; k2 < 8; k2++) {
                const float* pk = pb + k2 * 768;
                az += pk[0];
                ar += pk[128];
                ah += pk[256];
            }
            float z  = sigm(xz + az);
            float rr = sigm(xr + ar);
            float hh = fmaxf(xh + rr * ah, 0.0f);
            hprev = z * hprev + (1.0f - z) * hh;
            hs[r_g * UU + c_g] = hprev;
            if (seqout)
                seqout[((size_t)(row0 + r_g) * TT + step) * UU + c_g] = hprev;
        }
        __syncthreads();
    }

    if (t < 256) {
        hfin1[(size_t)(row0 + r_g) * UU + c_g] = hprev;
        if (hfin2) hfin2[(size_t)(row0 + r_g) * UU + c_g] = hprev;
    }
}

// =====================================================================
// launch
// =====================================================================
extern "C" void kernel_launch(void* const* d_in, const int* in_sizes, int n_in,
                              void* d_out, int out_size)
{
    (void)in_sizes; (void)n_in; (void)out_size;
    const float* input = (const float*)d_in[0];  // [256,1024,64]
    const float* W1    = (const float*)d_in[1];  // [64,384]
    const float* U1    = (const float*)d_in[2];  // [128,384]
    const float* b1    = (const float*)d_in[3];  // [2,384]
    const float* W2    = (const float*)d_in[4];  // [128,384]
    const float* U2    = (const float*)d_in[5];  // [128,384]
    const float* b2    = (const float*)d_in[6];  // [2,384]
    float* out = (float*)d_out;                  // [3*256*128]: x | state1 | state2

    float *xw1, *seq1, *xw2;
    cudaGetSymbolAddress((void**)&xw1,  g_xw1);
    cudaGetSymbolAddress((void**)&seq1, g_seq1);
    cudaGetSymbolAddress((void**)&xw2,  g_xw2);

    const int SMEM_G1 = 64 * 1536 + 24576 + 2048;    // 124928
    const int SMEM_G2 = 128 * 1536 + 24576 + 4096;   // 225280
    const int SMEM_S  = 196608 + 24576 + 1024;       // 222208

    cudaFuncSetAttribute(gemm_kernel<16>, cudaFuncAttributeMaxDynamicSharedMemorySize, SMEM_G1);
    cudaFuncSetAttribute(gemm_kernel<32>, cudaFuncAttributeMaxDynamicSharedMemorySize, SMEM_G2);
    cudaFuncSetAttribute(scan_kernel,     cudaFuncAttributeMaxDynamicSharedMemorySize, SMEM_S);

    const int nblk = (BB * TT) / 4;  // 65536 row-blocks of 4

    // Layer 1 input projection: xw1 = input @ W1 + b1[0]
    gemm_kernel<16><<<148, 384, SMEM_G1>>>(input, W1, b1, xw1, nblk);
    // Layer 1 scan: seq1, state1
    scan_kernel<<<128, 768, SMEM_S>>>(xw1, U1, b1 + G3,
                                      seq1, out + 32768, nullptr);
    // Layer 2 input projection: xw2 = seq1 @ W2 + b2[0]
    gemm_kernel<32><<<148, 384, SMEM_G2>>>(seq1, W2, b2, xw2, nblk);
    // Layer 2 scan: x (== state2)
    scan_kernel<<<128, 768, SMEM_S>>>(xw2, U2, b2 + G3,
                                      nullptr, out, out + 65536);
}

// round 10
// speedup vs baseline: 1.8934x; 1.3543x over previous
#include <cuda_runtime.h>

typedef unsigned long long ULL;

#define BB 256
#define TT 1024
#define FF 64
#define UU 128
#define G3 384   // 3*U

// ---------------- scratch buffers (no cudaMalloc allowed) ----------------
static __device__ float g_xw1[(size_t)BB * TT * G3];   // input proj layer1 [B,T,384]
static __device__ float g_seq1[(size_t)BB * TT * UU];  // layer1 hidden seq [B,T,128]
static __device__ float g_xw2[(size_t)BB * TT * G3];   // input proj layer2 [B,T,384]

// ---------------- helpers ----------------
__device__ __forceinline__ ULL fma2(ULL a, ULL b, ULL c) {
    ULL d;
    asm("fma.rn.f32x2 %0, %1, %2, %3;" : "=l"(d) : "l"(a), "l"(b), "l"(c));
    return d;
}
__device__ __forceinline__ ULL pack2(float lo, float hi) {
    ULL d;
    asm("mov.b64 %0, {%1, %2};" : "=l"(d) : "f"(lo), "f"(hi));
    return d;
}
__device__ __forceinline__ float4 add4(float4 a, float4 b) {
    return make_float4(a.x + b.x, a.y + b.y, a.z + b.z, a.w + b.w);
}
__device__ __forceinline__ float sigm(float x) {
    return 1.0f / (1.0f + __expf(-x));
}

// =====================================================================
// GEMM v2: out[M,384] = X[M,K] @ W[K,384] + bias,  K = 4*KC
// 8 rows/block (W read once per 8 rows), paired uniform LDS.128
// x-loads (2 k's / wavefront). PASSES-split partial reduce to fit smem.
// 384 threads: kg = t/96 (K/4-slice), cq = t%96 (column quad).
// =====================================================================
template <int KC, int PASSES>
__global__ void __launch_bounds__(384, 1) gemm_kernel(
    const float* __restrict__ X, const float* __restrict__ W,
    const float* __restrict__ bias, float* __restrict__ out, int nblk)
{
    constexpr int K = 4 * KC;
    constexpr int ROWS = 8;
    constexpr int RPP = ROWS / PASSES;          // rows per reduce pass

    extern __shared__ char smem[];
    // layout: W [K][96]f4 | bias [96]f4 | xp [8*K] ULL | part [4*RPP*96] ull2
    float4*     Wf4   = (float4*)smem;
    const ulonglong2* Ws2 = (const ulonglong2*)smem;
    float4*     bias_s = (float4*)(smem + (size_t)K * 1536);
    ULL*        xp    = (ULL*)(smem + (size_t)K * 1536 + 1536);
    ulonglong2* part  = (ulonglong2*)(smem + (size_t)K * 1536 + 1536 + 8 * K * 8);
    const float4* partf = (const float4*)part;

    const int t  = threadIdx.x;
    const int cq = t % 96;
    const int kg = t / 96;
    const int kbase = kg * KC;

    for (int i = t; i < K * 96; i += 384) Wf4[i] = ((const float4*)W)[i];
    if (t < 96) bias_s[t] = ((const float4*)bias)[t];
    __syncthreads();

    const ulonglong2* Up = Ws2 + (size_t)kbase * 96 + cq;

    for (int blk = blockIdx.x; blk < nblk; blk += gridDim.x) {
        const int row0 = blk * ROWS;
        // stage x packed (v,v), coalesced
        for (int i = t; i < ROWS * K; i += 384) {
            float v = X[(size_t)row0 * K + i];
            xp[i] = pack2(v, v);
        }
        __syncthreads();

        ULL acc[ROWS][2];
#pragma unroll
        for (int r = 0; r < ROWS; r++) { acc[r][0] = 0ull; acc[r][1] = 0ull; }

#pragma unroll
        for (int p = 0; p < KC / 2; p++) {
            ulonglong2 u0 = Up[(2 * p) * 96];
            ulonglong2 u1 = Up[(2 * p + 1) * 96];
#pragma unroll
            for (int r = 0; r < ROWS; r++) {
                // uniform LDS.128: packed (v,v) for k=2p and k=2p+1
                ulonglong2 xv = *(const ulonglong2*)&xp[r * K + kbase + 2 * p];
                acc[r][0] = fma2(u0.x, xv.x, acc[r][0]);
                acc[r][1] = fma2(u0.y, xv.x, acc[r][1]);
                acc[r][0] = fma2(u1.x, xv.y, acc[r][0]);
                acc[r][1] = fma2(u1.y, xv.y, acc[r][1]);
            }
        }

#pragma unroll
        for (int pass = 0; pass < PASSES; pass++) {
#pragma unroll
            for (int rr = 0; rr < RPP; rr++)
                part[(kg * RPP + rr) * 96 + cq] =
                    make_ulonglong2(acc[pass * RPP + rr][0], acc[pass * RPP + rr][1]);
            __syncthreads();
            for (int slot = t; slot < RPP * 96; slot += 384) {
                int rloc = slot / 96, cqq = slot % 96;
                float4 s = bias_s[cqq];
#pragma unroll
                for (int kg2 = 0; kg2 < 4; kg2++)
                    s = add4(s, partf[(kg2 * RPP + rloc) * 96 + cqq]);
                ((float4*)out)[(size_t)(row0 + pass * RPP + rloc) * 96 + cqq] = s;
            }
            __syncthreads();
        }
    }
}

// =====================================================================
// GRU scan v7: hybrid register/smem U. 128 CTAs x 2 rows, 384 threads.
// kg = t/96 (k-slice of 32), cq = t%96. Per thread:
//   k = kbase..kbase+15 : U in registers (32 regs as 16 x 2 ULL)
//   k = kbase+16..+31   : U streamed from smem (768 wf/step total)
// h broadcast via shfl (2 source regs per lane). Partials [4][2][96];
// 256-thread gate tail; 2 barriers/step.
// =====================================================================
__global__ void __launch_bounds__(384, 1) scan_kernel(
    const float* __restrict__ xw,       // [B,T,384]
    const float* __restrict__ Urec,     // [128,384]
    const float* __restrict__ rbias,    // [384]
    float* __restrict__ seqout,         // [B,T,128] or null
    float* __restrict__ hfin1,          // [B,128]
    float* __restrict__ hfin2)          // optional second copy or null
{
    extern __shared__ char smem[];
    ulonglong2* Ust = (ulonglong2*)smem;                 // [16 j'][4 kg][96 cq] 98304 B
    ulonglong2* part = (ulonglong2*)(smem + 98304);      // [4 kg][2 row][96]   12288 B
    const float* partF = (const float*)(smem + 98304);
    float*      hs   = (float*)(smem + 98304 + 12288);   // [2][128]             1024 B

    const int t    = threadIdx.x;
    const int lane = t & 31;
    const int cq   = t % 96;
    const int kg   = t / 96;            // 0..3
    const int kbase = kg * 32;
    const int row0 = blockIdx.x * 2;
    const int r_g = t >> 7;             // gate row (t<256)
    const int c_g = t & 127;            // gate column

    // hoist U[k = kbase..kbase+15][4cq..4cq+3] into registers
    ULL Ureg[16][2];
#pragma unroll
    for (int j = 0; j < 16; j++) {
        ulonglong2 uv = ((const ulonglong2*)(Urec + (size_t)(kbase + j) * G3))[cq];
        Ureg[j][0] = uv.x; Ureg[j][1] = uv.y;
    }
    // stage streamed half: k = kbase+16..+31
    for (int jj = 0; jj < 16; jj++) {
        Ust[(jj * 4 + kg) * 96 + cq] =
            ((const ulonglong2*)(Urec + (size_t)(kbase + 16 + jj) * G3))[cq];
    }

    float4 bq = ((const float4*)rbias)[cq];
    ULL b01 = (kg == 0) ? pack2(bq.x, bq.y) : 0ull;
    ULL b23 = (kg == 0) ? pack2(bq.z, bq.w) : 0ull;

    if (t < 256) hs[t] = 0.0f;
    float hprev = 0.0f;
    __syncthreads();

    const ulonglong2* UstP = Ust + kg * 96 + cq;   // index j': UstP[j'*384]
    const int hrow = lane >> 4;                    // 0..1 (source role)
    const int hk0  = kbase + (lane & 15);
    const int hk1  = kbase + 16 + (lane & 15);

    for (int step = 0; step < TT; ++step) {
        // gate threads prefetch xw (consumed after mainloop)
        float xz = 0.f, xr = 0.f, xh = 0.f;
        if (t < 256) {
            const float* p = xw + ((size_t)(row0 + r_g) * TT + step) * G3 + c_g;
            xz = p[0]; xr = p[128]; xh = p[256];
        }

        float h_f0 = hs[hrow * UU + hk0];
        float h_f1 = hs[hrow * UU + hk1];

        ULL a00 = b01, a01 = b23;   // row0
        ULL a10 = b01, a11 = b23;   // row1
#pragma unroll
        for (int j = 0; j < 16; j++) {
            float hA = __shfl_sync(0xffffffffu, h_f0, j);        // row0, k=kbase+j
            float hB = __shfl_sync(0xffffffffu, h_f0, 16 + j);   // row1
            ULL ha2 = pack2(hA, hA);
            ULL hb2 = pack2(hB, hB);
            a00 = fma2(Ureg[j][0], ha2, a00);
            a01 = fma2(Ureg[j][1], ha2, a01);
            a10 = fma2(Ureg[j][0], hb2, a10);
            a11 = fma2(Ureg[j][1], hb2, a11);
        }
#pragma unroll
        for (int jj = 0; jj < 16; jj++) {
            ulonglong2 u = UstP[jj * 384];
            float hA = __shfl_sync(0xffffffffu, h_f1, jj);       // row0, k=kbase+16+jj
            float hB = __shfl_sync(0xffffffffu, h_f1, 16 + jj);  // row1
            ULL ha2 = pack2(hA, hA);
            ULL hb2 = pack2(hB, hB);
            a00 = fma2(u.x, ha2, a00);
            a01 = fma2(u.y, ha2, a01);
            a10 = fma2(u.x, hb2, a10);
            a11 = fma2(u.y, hb2, a11);
        }
        part[(kg * 2 + 0) * 96 + cq] = make_ulonglong2(a00, a01);
        part[(kg * 2 + 1) * 96 + cq] = make_ulonglong2(a10, a11);
        __syncthreads();

        if (t < 256) {
            const float* pb = partF + r_g * 384 + c_g;
            float az = 0.f, ar = 0.f, ah = 0.f;
#pragma unroll
            for (int k2 = 0; k2 < 4; k2++) {
                const float* pk = pb + k2 * 768;
                az += pk[0];
                ar += pk[128];
                ah += pk[256];
            }
            float z  = sigm(xz + az);
            float rr = sigm(xr + ar);
            float hh = fmaxf(xh + rr * ah, 0.0f);
            hprev = z * hprev + (1.0f - z) * hh;
            hs[r_g * UU + c_g] = hprev;
            if (seqout)
                seqout[((size_t)(row0 + r_g) * TT + step) * UU + c_g] = hprev;
        }
        __syncthreads();
    }

    if (t < 256) {
        hfin1[(size_t)(row0 + r_g) * UU + c_g] = hprev;
        if (hfin2) hfin2[(size_t)(row0 + r_g) * UU + c_g] = hprev;
    }
}

// =====================================================================
// launch
// =====================================================================
extern "C" void kernel_launch(void* const* d_in, const int* in_sizes, int n_in,
                              void* d_out, int out_size)
{
    (void)in_sizes; (void)n_in; (void)out_size;
    const float* input = (const float*)d_in[0];  // [256,1024,64]
    const float* W1    = (const float*)d_in[1];  // [64,384]
    const float* U1    = (const float*)d_in[2];  // [128,384]
    const float* b1    = (const float*)d_in[3];  // [2,384]
    const float* W2    = (const float*)d_in[4];  // [128,384]
    const float* U2    = (const float*)d_in[5];  // [128,384]
    const float* b2    = (const float*)d_in[6];  // [2,384]
    float* out = (float*)d_out;                  // [3*256*128]: x | state1 | state2

    float *xw1, *seq1, *xw2;
    cudaGetSymbolAddress((void**)&xw1,  g_xw1);
    cudaGetSymbolAddress((void**)&seq1, g_seq1);
    cudaGetSymbolAddress((void**)&xw2,  g_xw2);

    // smem: W(K*1536) + bias 1536 + xp(8K*8) + part(4*RPP*96*16)
    const int SMEM_G1 = 64 * 1536 + 1536 + 8 * 64 * 8 + 4 * 8 * 96 * 16;   // 153088
    const int SMEM_G2 = 128 * 1536 + 1536 + 8 * 128 * 8 + 4 * 4 * 96 * 16; // 230912
    const int SMEM_S  = 98304 + 12288 + 1024;                              // 111616

    cudaFuncSetAttribute(gemm_kernel<16, 1>, cudaFuncAttributeMaxDynamicSharedMemorySize, SMEM_G1);
    cudaFuncSetAttribute(gemm_kernel<32, 2>, cudaFuncAttributeMaxDynamicSharedMemorySize, SMEM_G2);
    cudaFuncSetAttribute(scan_kernel,        cudaFuncAttributeMaxDynamicSharedMemorySize, SMEM_S);

    const int nblk = (BB * TT) / 8;  // 32768 row-blocks of 8

    // Layer 1 input projection: xw1 = input @ W1 + b1[0]
    gemm_kernel<16, 1><<<148, 384, SMEM_G1>>>(input, W1, b1, xw1, nblk);
    // Layer 1 scan: seq1, state1
    scan_kernel<<<128, 384, SMEM_S>>>(xw1, U1, b1 + G3,
                                      seq1, out + 32768, nullptr);
    // Layer 2 input projection: xw2 = seq1 @ W2 + b2[0]
    gemm_kernel<32, 2><<<148, 384, SMEM_G2>>>(seq1, W2, b2, xw2, nblk);
    // Layer 2 scan: x (== state2)
    scan_kernel<<<128, 384, SMEM_S>>>(xw2, U2, b2 + G3,
                                      nullptr, out, out + 65536);
}

// round 13
// speedup vs baseline: 2.0762x; 1.0965x over previous
#include <cuda_runtime.h>

typedef unsigned long long ULL;

#define BB 256
#define TT 1024
#define FF 64
#define UU 128
#define G3 384   // 3*U

// ---------------- scratch buffers (no cudaMalloc allowed) ----------------
static __device__ float g_xw1[(size_t)BB * TT * G3];   // input proj layer1 [B,T,384]
static __device__ float g_seq1[(size_t)BB * TT * UU];  // layer1 hidden seq [B,T,128]
static __device__ float g_xw2[(size_t)BB * TT * G3];   // input proj layer2 [B,T,384]

// ---------------- helpers ----------------
__device__ __forceinline__ ULL fma2(ULL a, ULL b, ULL c) {
    ULL d;
    asm("fma.rn.f32x2 %0, %1, %2, %3;" : "=l"(d) : "l"(a), "l"(b), "l"(c));
    return d;
}
__device__ __forceinline__ ULL pack2(float lo, float hi) {
    ULL d;
    asm("mov.b64 %0, {%1, %2};" : "=l"(d) : "f"(lo), "f"(hi));
    return d;
}
__device__ __forceinline__ float4 add4(float4 a, float4 b) {
    return make_float4(a.x + b.x, a.y + b.y, a.z + b.z, a.w + b.w);
}
__device__ __forceinline__ float sigm(float x) {
    return 1.0f / (1.0f + __expf(-x));
}

// =====================================================================
// GEMM v3: out[M,384] = X[M,K] @ W[K,384] + bias,  K = 4*KC
// 16 rows/block; W resident in smem (read once per 16 rows);
// x staged packed (v,v), read via uniform LDS.128 (2 k's / wavefront).
// PASSES-split partial reduce sized to fit 227KB smem.
// 384 threads: kg = t/96 (K/4 slice), cq = t%96 (column quad).
// =====================================================================
template <int KC, int PASSES>
__global__ void __launch_bounds__(384, 1) gemm_kernel(
    const float* __restrict__ X, const float* __restrict__ W,
    const float* __restrict__ bias, float* __restrict__ out, int nblk)
{
    constexpr int K = 4 * KC;
    constexpr int ROWS = 16;
    constexpr int RPP = ROWS / PASSES;          // rows per reduce pass

    extern __shared__ char smem[];
    float4*     Wf4   = (float4*)smem;                                   // [K][96]
    const ulonglong2* Ws2 = (const ulonglong2*)smem;
    float4*     bias_s = (float4*)(smem + (size_t)K * 1536);             // [96]
    ULL*        xp    = (ULL*)(smem + (size_t)K * 1536 + 1536);          // [ROWS*K]
    ulonglong2* part  = (ulonglong2*)(smem + (size_t)K * 1536 + 1536 + ROWS * K * 8);
    const float4* partf = (const float4*)part;                           // [4*RPP][96]

    const int t  = threadIdx.x;
    const int cq = t % 96;
    const int kg = t / 96;
    const int kbase = kg * KC;

    for (int i = t; i < K * 96; i += 384) Wf4[i] = ((const float4*)W)[i];
    if (t < 96) bias_s[t] = ((const float4*)bias)[t];
    __syncthreads();

    const ulonglong2* Up = Ws2 + (size_t)kbase * 96 + cq;

    for (int blk = blockIdx.x; blk < nblk; blk += gridDim.x) {
        const int row0 = blk * ROWS;
        // stage x packed (v,v), coalesced
        for (int i = t; i < ROWS * K; i += 384) {
            float v = X[(size_t)row0 * K + i];
            xp[i] = pack2(v, v);
        }
        __syncthreads();

        ULL acc[ROWS][2];
#pragma unroll
        for (int r = 0; r < ROWS; r++) { acc[r][0] = 0ull; acc[r][1] = 0ull; }

#pragma unroll
        for (int p = 0; p < KC / 2; p++) {
            ulonglong2 u0 = Up[(2 * p) * 96];
            ulonglong2 u1 = Up[(2 * p + 1) * 96];
#pragma unroll
            for (int r = 0; r < ROWS; r++) {
                // uniform LDS.128: packed (v,v) for k=2p and k=2p+1
                ulonglong2 xv = *(const ulonglong2*)&xp[r * K + kbase + 2 * p];
                acc[r][0] = fma2(u0.x, xv.x, acc[r][0]);
                acc[r][1] = fma2(u0.y, xv.x, acc[r][1]);
                acc[r][0] = fma2(u1.x, xv.y, acc[r][0]);
                acc[r][1] = fma2(u1.y, xv.y, acc[r][1]);
            }
        }

#pragma unroll
        for (int pass = 0; pass < PASSES; pass++) {
#pragma unroll
            for (int rr = 0; rr < RPP; rr++)
                part[(kg * RPP + rr) * 96 + cq] =
                    make_ulonglong2(acc[pass * RPP + rr][0], acc[pass * RPP + rr][1]);
            __syncthreads();
            for (int slot = t; slot < RPP * 96; slot += 384) {
                int rloc = slot / 96, cqq = slot % 96;
                float4 s = bias_s[cqq];
#pragma unroll
                for (int kg2 = 0; kg2 < 4; kg2++)
                    s = add4(s, partf[(kg2 * RPP + rloc) * 96 + cqq]);
                ((float4*)out)[(size_t)(row0 + pass * RPP + rloc) * 96 + cqq] = s;
            }
            __syncthreads();
        }
    }
}

// =====================================================================
// GRU scan v8: hybrid register/smem U, NO shfl (h via uniform-LDS
// broadcast of packed (h,h) pairs). 128 CTAs x 2 rows, 384 threads.
// kg = t/96 (k-slice of 32), cq = t%96:
//   k = kbase..kbase+19 : U in registers (40 ULL = 80 regs)
//   k = kbase+20..+31   : U streamed from smem (576 wf/step)
// h broadcast: uniform LDS.128 -> 2 packed k's (384 wf/step).
// Partials [4][2][96]; 256-thread gate tail; 2 barriers/step.
// =====================================================================
#define HOIST 20
#define STRM  12

__global__ void __launch_bounds__(384, 1) scan_kernel(
    const float* __restrict__ xw,       // [B,T,384]
    const float* __restrict__ Urec,     // [128,384]
    const float* __restrict__ rbias,    // [384]
    float* __restrict__ seqout,         // [B,T,128] or null
    float* __restrict__ hfin1,          // [B,128]
    float* __restrict__ hfin2)          // optional second copy or null
{
    extern __shared__ char smem[];
    ulonglong2* Ust = (ulonglong2*)smem;                 // [STRM][4 kg][96 cq] 73728 B
    ulonglong2* part = (ulonglong2*)(smem + 73728);      // [4 kg][2 row][96]   12288 B
    const float* partF = (const float*)(smem + 73728);
    ULL*        hs   = (ULL*)(smem + 73728 + 12288);     // [2][128] packed (h,h) 2048 B

    const int t    = threadIdx.x;
    const int cq   = t % 96;
    const int kg   = t / 96;            // 0..3
    const int kbase = kg * 32;
    const int row0 = blockIdx.x * 2;
    const int r_g = t >> 7;             // gate row (t<256)
    const int c_g = t & 127;            // gate column

    // hoist U[k = kbase..kbase+HOIST-1][4cq..4cq+3] into registers
    ULL Ureg[HOIST][2];
#pragma unroll
    for (int j = 0; j < HOIST; j++) {
        ulonglong2 uv = ((const ulonglong2*)(Urec + (size_t)(kbase + j) * G3))[cq];
        Ureg[j][0] = uv.x; Ureg[j][1] = uv.y;
    }
    // stage streamed tail: k = kbase+HOIST .. kbase+31
    for (int jj = 0; jj < STRM; jj++) {
        Ust[(jj * 4 + kg) * 96 + cq] =
            ((const ulonglong2*)(Urec + (size_t)(kbase + HOIST + jj) * G3))[cq];
    }

    float4 bq = ((const float4*)rbias)[cq];
    ULL b01 = (kg == 0) ? pack2(bq.x, bq.y) : 0ull;
    ULL b23 = (kg == 0) ? pack2(bq.z, bq.w) : 0ull;

    if (t < 256) hs[t] = 0ull;
    float hprev = 0.0f;
    __syncthreads();

    const ulonglong2* UstP = Ust + kg * 96 + cq;   // stride 384 per jj
    // uniform h-pair views (k pairs within this thread's k-slice)
    const ulonglong2* h0v = (const ulonglong2*)&hs[0 * UU + kbase];
    const ulonglong2* h1v = (const ulonglong2*)&hs[1 * UU + kbase];

    for (int step = 0; step < TT; ++step) {
        // gate threads prefetch xw (consumed after mainloop)
        float xz = 0.f, xr = 0.f, xh = 0.f;
        if (t < 256) {
            const float* p = xw + ((size_t)(row0 + r_g) * TT + step) * G3 + c_g;
            xz = p[0]; xr = p[128]; xh = p[256];
        }

        ULL a00 = b01, a01 = b23;   // row0, col pairs (4cq,4cq+1),(4cq+2,4cq+3)
        ULL a10 = b01, a11 = b23;   // row1

        // hoisted half: HOIST/2 = 10 k-pairs, h via uniform LDS.128
#pragma unroll
        for (int jp = 0; jp < HOIST / 2; jp++) {
            ulonglong2 ha = h0v[jp];        // (h,h) k=kbase+2jp, k+1  row0
            ulonglong2 hb = h1v[jp];        // row1
            a00 = fma2(Ureg[2 * jp][0],     ha.x, a00);
            a01 = fma2(Ureg[2 * jp][1],     ha.x, a01);
            a10 = fma2(Ureg[2 * jp][0],     hb.x, a10);
            a11 = fma2(Ureg[2 * jp][1],     hb.x, a11);
            a00 = fma2(Ureg[2 * jp + 1][0], ha.y, a00);
            a01 = fma2(Ureg[2 * jp + 1][1], ha.y, a01);
            a10 = fma2(Ureg[2 * jp + 1][0], hb.y, a10);
            a11 = fma2(Ureg[2 * jp + 1][1], hb.y, a11);
        }
        // streamed half: STRM/2 = 6 k-pairs
#pragma unroll
        for (int jp = 0; jp < STRM / 2; jp++) {
            ulonglong2 u0 = UstP[(2 * jp) * 384];
            ulonglong2 u1 = UstP[(2 * jp + 1) * 384];
            ulonglong2 ha = h0v[HOIST / 2 + jp];
            ulonglong2 hb = h1v[HOIST / 2 + jp];
            a00 = fma2(u0.x, ha.x, a00);
            a01 = fma2(u0.y, ha.x, a01);
            a10 = fma2(u0.x, hb.x, a10);
            a11 = fma2(u0.y, hb.x, a11);
            a00 = fma2(u1.x, ha.y, a00);
            a01 = fma2(u1.y, ha.y, a01);
            a10 = fma2(u1.x, hb.y, a10);
            a11 = fma2(u1.y, hb.y, a11);
        }
        part[(kg * 2 + 0) * 96 + cq] = make_ulonglong2(a00, a01);
        part[(kg * 2 + 1) * 96 + cq] = make_ulonglong2(a10, a11);
        __syncthreads();

        if (t < 256) {
            const float* pb = partF + r_g * 384 + c_g;
            float az = 0.f, ar = 0.f, ah = 0.f;
#pragma unroll
            for (int k2 = 0; k2 < 4; k2++) {
                const float* pk = pb + k2 * 768;
                az += pk[0];
                ar += pk[128];
                ah += pk[256];
            }
            float z  = sigm(xz + az);
            float rr = sigm(xr + ar);
            float hh = fmaxf(xh + rr * ah, 0.0f);
            hprev = z * hprev + (1.0f - z) * hh;
            hs[r_g * UU + c_g] = pack2(hprev, hprev);
            if (seqout)
                seqout[((size_t)(row0 + r_g) * TT + step) * UU + c_g] = hprev;
        }
        __syncthreads();
    }

    if (t < 256) {
        hfin1[(size_t)(row0 + r_g) * UU + c_g] = hprev;
        if (hfin2) hfin2[(size_t)(row0 + r_g) * UU + c_g] = hprev;
    }
}

// =====================================================================
// launch
// =====================================================================
extern "C" void kernel_launch(void* const* d_in, const int* in_sizes, int n_in,
                              void* d_out, int out_size)
{
    (void)in_sizes; (void)n_in; (void)out_size;
    const float* input = (const float*)d_in[0];  // [256,1024,64]
    const float* W1    = (const float*)d_in[1];  // [64,384]
    const float* U1    = (const float*)d_in[2];  // [128,384]
    const float* b1    = (const float*)d_in[3];  // [2,384]
    const float* W2    = (const float*)d_in[4];  // [128,384]
    const float* U2    = (const float*)d_in[5];  // [128,384]
    const float* b2    = (const float*)d_in[6];  // [2,384]
    float* out = (float*)d_out;                  // [3*256*128]: x | state1 | state2

    float *xw1, *seq1, *xw2;
    cudaGetSymbolAddress((void**)&xw1,  g_xw1);
    cudaGetSymbolAddress((void**)&seq1, g_seq1);
    cudaGetSymbolAddress((void**)&xw2,  g_xw2);

    // gemm smem: W(K*1536) + bias 1536 + xp(16*K*8) + part(4*RPP*96*16)
    const int SMEM_G1 = 64 * 1536 + 1536 + 16 * 64 * 8 + 4 * 16 * 96 * 16;  // 206336
    const int SMEM_G2 = 128 * 1536 + 1536 + 16 * 128 * 8 + 4 * 2 * 96 * 16; // 226816
    const int SMEM_S  = 73728 + 12288 + 2048;                               // 88064

    cudaFuncSetAttribute(gemm_kernel<16, 1>, cudaFuncAttributeMaxDynamicSharedMemorySize, SMEM_G1);
    cudaFuncSetAttribute(gemm_kernel<32, 8>, cudaFuncAttributeMaxDynamicSharedMemorySize, SMEM_G2);
    cudaFuncSetAttribute(scan_kernel,        cudaFuncAttributeMaxDynamicSharedMemorySize, SMEM_S);

    const int nblk = (BB * TT) / 16;  // 16384 row-blocks of 16

    // Layer 1 input projection: xw1 = input @ W1 + b1[0]
    gemm_kernel<16, 1><<<148, 384, SMEM_G1>>>(input, W1, b1, xw1, nblk);
    // Layer 1 scan: seq1, state1
    scan_kernel<<<128, 384, SMEM_S>>>(xw1, U1, b1 + G3,
                                      seq1, out + 32768, nullptr);
    // Layer 2 input projection: xw2 = seq1 @ W2 + b2[0]
    gemm_kernel<32, 8><<<148, 384, SMEM_G2>>>(seq1, W2, b2, xw2, nblk);
    // Layer 2 scan: x (== state2)
    scan_kernel<<<128, 384, SMEM_S>>>(xw2, U2, b2 + G3,
                                      nullptr, out, out + 65536);
}

// round 15
// speedup vs baseline: 2.1841x; 1.0520x over previous
#include <cuda_runtime.h>

typedef unsigned long long ULL;

#define BB 256
#define TT 1024
#define FF 64
#define UU 128
#define G3 384   // 3*U

// ---------------- scratch buffers (no cudaMalloc allowed) ----------------
static __device__ float g_xw1[(size_t)BB * TT * G3];   // input proj layer1 [B,T,384]
static __device__ float g_seq1[(size_t)BB * TT * UU];  // layer1 hidden seq [B,T,128]
static __device__ float g_xw2[(size_t)BB * TT * G3];   // input proj layer2 [B,T,384]

// ---------------- helpers ----------------
__device__ __forceinline__ ULL fma2(ULL a, ULL b, ULL c) {
    ULL d;
    asm("fma.rn.f32x2 %0, %1, %2, %3;" : "=l"(d) : "l"(a), "l"(b), "l"(c));
    return d;
}
__device__ __forceinline__ ULL pack2(float lo, float hi) {
    ULL d;
    asm("mov.b64 %0, {%1, %2};" : "=l"(d) : "f"(lo), "f"(hi));
    return d;
}
__device__ __forceinline__ float4 add4(float4 a, float4 b) {
    return make_float4(a.x + b.x, a.y + b.y, a.z + b.z, a.w + b.w);
}
__device__ __forceinline__ float sigm(float x) {
    return 1.0f / (1.0f + __expf(-x));
}

// =====================================================================
// GEMM v4: out[M,384] = X[M,K] @ W[K,384] + bias,  K = 8*KC8
// 768 threads (6 warps/SMSP for latency hiding), 8 rows/block.
// kg = t/96 (K/8 slice), cq = t%96 (column quad).
// W resident in smem; x staged packed (v,v), read via uniform LDS.128.
// Partial buffer OVERLAID on the dead xp region; PASSES-split reduce.
// =====================================================================
template <int KC8, int PASSES>
__global__ void __launch_bounds__(768, 1) gemm_kernel(
    const float* __restrict__ X, const float* __restrict__ W,
    const float* __restrict__ bias, float* __restrict__ out, int nblk)
{
    constexpr int K = 8 * KC8;
    constexpr int ROWS = 8;
    constexpr int RPP = ROWS / PASSES;          // rows per reduce pass

    extern __shared__ char smem[];
    float4*     Wf4   = (float4*)smem;                                   // [K][96]
    const ulonglong2* Ws2 = (const ulonglong2*)smem;
    float4*     bias_s = (float4*)(smem + (size_t)K * 1536);             // [96]
    // overlay region: xp [ROWS*K] ULL  and  part [8*RPP*96] ull2
    ULL*        xp    = (ULL*)(smem + (size_t)K * 1536 + 1536);
    ulonglong2* part  = (ulonglong2*)(smem + (size_t)K * 1536 + 1536);
    const float4* partf = (const float4*)part;

    const int t  = threadIdx.x;
    const int cq = t % 96;
    const int kg = t / 96;                      // 0..7
    const int kbase = kg * KC8;

    for (int i = t; i < K * 96; i += 768) Wf4[i] = ((const float4*)W)[i];
    if (t < 96) bias_s[t] = ((const float4*)bias)[t];
    __syncthreads();

    const ulonglong2* Up = Ws2 + (size_t)kbase * 96 + cq;

    for (int blk = blockIdx.x; blk < nblk; blk += gridDim.x) {
        const int row0 = blk * ROWS;
        // stage x packed (v,v), coalesced
        for (int i = t; i < ROWS * K; i += 768) {
            float v = X[(size_t)row0 * K + i];
            xp[i] = pack2(v, v);
        }
        __syncthreads();

        ULL acc[ROWS][2];
#pragma unroll
        for (int r = 0; r < ROWS; r++) { acc[r][0] = 0ull; acc[r][1] = 0ull; }

#pragma unroll
        for (int p = 0; p < KC8 / 2; p++) {
            ulonglong2 u0 = Up[(2 * p) * 96];
            ulonglong2 u1 = Up[(2 * p + 1) * 96];
#pragma unroll
            for (int r = 0; r < ROWS; r++) {
                // uniform LDS.128: packed (v,v) for k=2p and k=2p+1
                ulonglong2 xv = *(const ulonglong2*)&xp[r * K + kbase + 2 * p];
                acc[r][0] = fma2(u0.x, xv.x, acc[r][0]);
                acc[r][1] = fma2(u0.y, xv.x, acc[r][1]);
                acc[r][0] = fma2(u1.x, xv.y, acc[r][0]);
                acc[r][1] = fma2(u1.y, xv.y, acc[r][1]);
            }
        }
        __syncthreads();   // all xp reads done before part STS overlays it

#pragma unroll
        for (int pass = 0; pass < PASSES; pass++) {
#pragma unroll
            for (int rr = 0; rr < RPP; rr++)
                part[(kg * RPP + rr) * 96 + cq] =
                    make_ulonglong2(acc[pass * RPP + rr][0], acc[pass * RPP + rr][1]);
            __syncthreads();
            for (int slot = t; slot < RPP * 96; slot += 768) {
                int rloc = slot / 96, cqq = slot % 96;
                float4 s = bias_s[cqq];
#pragma unroll
                for (int kg2 = 0; kg2 < 8; kg2++)
                    s = add4(s, partf[(kg2 * RPP + rloc) * 96 + cqq]);
                ((float4*)out)[(size_t)(row0 + pass * RPP + rloc) * 96 + cqq] = s;
            }
            __syncthreads();
        }
    }
}

// =====================================================================
// GRU scan v9: hybrid register/smem U; h stored PLAIN and loaded as
// uniform float4 (4 k's per wavefront), duplicated into (h,h) packs on
// the ALU pipe. 128 CTAs x 2 rows, 384 threads.
// kg = t/96 (k-slice of 32), cq = t%96:
//   k = kbase..kbase+19 : U in registers (40 ULL = 80 regs)
//   k = kbase+20..+31   : U streamed from smem (576 wf/step)
// h loads: 16 uniform LDS.128 (192 wf/step) + 64 pack2.
// Partials [4][2][96]; 256-thread gate tail; 2 barriers/step.
// =====================================================================
#define HOIST 20
#define STRM  12

__global__ void __launch_bounds__(384, 1) scan_kernel(
    const float* __restrict__ xw,       // [B,T,384]
    const float* __restrict__ Urec,     // [128,384]
    const float* __restrict__ rbias,    // [384]
    float* __restrict__ seqout,         // [B,T,128] or null
    float* __restrict__ hfin1,          // [B,128]
    float* __restrict__ hfin2)          // optional second copy or null
{
    extern __shared__ char smem[];
    ulonglong2* Ust = (ulonglong2*)smem;                 // [STRM][4 kg][96 cq] 73728 B
    ulonglong2* part = (ulonglong2*)(smem + 73728);      // [4 kg][2 row][96]   12288 B
    const float* partF = (const float*)(smem + 73728);
    float*      hs   = (float*)(smem + 73728 + 12288);   // [2][128] plain       1024 B

    const int t    = threadIdx.x;
    const int cq   = t % 96;
    const int kg   = t / 96;            // 0..3
    const int kbase = kg * 32;
    const int row0 = blockIdx.x * 2;
    const int r_g = t >> 7;             // gate row (t<256)
    const int c_g = t & 127;            // gate column

    // hoist U[k = kbase..kbase+HOIST-1][4cq..4cq+3] into registers
    ULL Ureg[HOIST][2];
#pragma unroll
    for (int j = 0; j < HOIST; j++) {
        ulonglong2 uv = ((const ulonglong2*)(Urec + (size_t)(kbase + j) * G3))[cq];
        Ureg[j][0] = uv.x; Ureg[j][1] = uv.y;
    }
    // stage streamed tail: k = kbase+HOIST .. kbase+31
    for (int jj = 0; jj < STRM; jj++) {
        Ust[(jj * 4 + kg) * 96 + cq] =
            ((const ulonglong2*)(Urec + (size_t)(kbase + HOIST + jj) * G3))[cq];
    }

    float4 bq = ((const float4*)rbias)[cq];
    ULL b01 = (kg == 0) ? pack2(bq.x, bq.y) : 0ull;
    ULL b23 = (kg == 0) ? pack2(bq.z, bq.w) : 0ull;

    if (t < 256) hs[t] = 0.0f;
    float hprev = 0.0f;
    __syncthreads();

    const ulonglong2* UstP = Ust + kg * 96 + cq;   // stride 384 per streamed k
    const float* h0f = hs + kbase;                 // row0 slice (uniform)
    const float* h1f = hs + UU + kbase;            // row1 slice

    for (int step = 0; step < TT; ++step) {
        // gate threads prefetch xw (consumed after mainloop)
        float xz = 0.f, xr = 0.f, xh = 0.f;
        if (t < 256) {
            const float* p = xw + ((size_t)(row0 + r_g) * TT + step) * G3 + c_g;
            xz = p[0]; xr = p[128]; xh = p[256];
        }

        ULL a00 = b01, a01 = b23;   // row0, col pairs (4cq,4cq+1),(4cq+2,4cq+3)
        ULL a10 = b01, a11 = b23;   // row1

        // hoisted: 5 groups of 4 k; h via uniform float4 + ALU duplication
#pragma unroll
        for (int g = 0; g < HOIST / 4; g++) {
            float4 ha4 = *(const float4*)&h0f[4 * g];
            float4 hb4 = *(const float4*)&h1f[4 * g];
            ULL ha, hb;
            ha = pack2(ha4.x, ha4.x); hb = pack2(hb4.x, hb4.x);
            a00 = fma2(Ureg[4 * g][0], ha, a00);
            a01 = fma2(Ureg[4 * g][1], ha, a01);
            a10 = fma2(Ureg[4 * g][0], hb, a10);
            a11 = fma2(Ureg[4 * g][1], hb, a11);
            ha = pack2(ha4.y, ha4.y); hb = pack2(hb4.y, hb4.y);
            a00 = fma2(Ureg[4 * g + 1][0], ha, a00);
            a01 = fma2(Ureg[4 * g + 1][1], ha, a01);
            a10 = fma2(Ureg[4 * g + 1][0], hb, a10);
            a11 = fma2(Ureg[4 * g + 1][1], hb, a11);
            ha = pack2(ha4.z, ha4.z); hb = pack2(hb4.z, hb4.z);
            a00 = fma2(Ureg[4 * g + 2][0], ha, a00);
            a01 = fma2(Ureg[4 * g + 2][1], ha, a01);
            a10 = fma2(Ureg[4 * g + 2][0], hb, a10);
            a11 = fma2(Ureg[4 * g + 2][1], hb, a11);
            ha = pack2(ha4.w, ha4.w); hb = pack2(hb4.w, hb4.w);
            a00 = fma2(Ureg[4 * g + 3][0], ha, a00);
            a01 = fma2(Ureg[4 * g + 3][1], ha, a01);
            a10 = fma2(Ureg[4 * g + 3][0], hb, a10);
            a11 = fma2(Ureg[4 * g + 3][1], hb, a11);
        }
        // streamed: 3 groups of 4 k
#pragma unroll
        for (int gg = 0; gg < STRM / 4; gg++) {
            float4 ha4 = *(const float4*)&h0f[HOIST + 4 * gg];
            float4 hb4 = *(const float4*)&h1f[HOIST + 4 * gg];
            ulonglong2 u0 = UstP[(4 * gg + 0) * 384];
            ulonglong2 u1 = UstP[(4 * gg + 1) * 384];
            ulonglong2 u2 = UstP[(4 * gg + 2) * 384];
            ulonglong2 u3 = UstP[(4 * gg + 3) * 384];
            ULL ha, hb;
            ha = pack2(ha4.x, ha4.x); hb = pack2(hb4.x, hb4.x);
            a00 = fma2(u0.x, ha, a00); a01 = fma2(u0.y, ha, a01);
            a10 = fma2(u0.x, hb, a10); a11 = fma2(u0.y, hb, a11);
            ha = pack2(ha4.y, ha4.y); hb = pack2(hb4.y, hb4.y);
            a00 = fma2(u1.x, ha, a00); a01 = fma2(u1.y, ha, a01);
            a10 = fma2(u1.x, hb, a10); a11 = fma2(u1.y, hb, a11);
            ha = pack2(ha4.z, ha4.z); hb = pack2(hb4.z, hb4.z);
            a00 = fma2(u2.x, ha, a00); a01 = fma2(u2.y, ha, a01);
            a10 = fma2(u2.x, hb, a10); a11 = fma2(u2.y, hb, a11);
            ha = pack2(ha4.w, ha4.w); hb = pack2(hb4.w, hb4.w);
            a00 = fma2(u3.x, ha, a00); a01 = fma2(u3.y, ha, a01);
            a10 = fma2(u3.x, hb, a10); a11 = fma2(u3.y, hb, a11);
        }
        part[(kg * 2 + 0) * 96 + cq] = make_ulonglong2(a00, a01);
        part[(kg * 2 + 1) * 96 + cq] = make_ulonglong2(a10, a11);
        __syncthreads();

        if (t < 256) {
            const float* pb = partF + r_g * 384 + c_g;
            float az = 0.f, ar = 0.f, ah = 0.f;
#pragma unroll
            for (int k2 = 0; k2 < 4; k2++) {
                const float* pk = pb + k2 * 768;
                az += pk[0];
                ar += pk[128];
                ah += pk[256];
            }
            float z  = sigm(xz + az);
            float rr = sigm(xr + ar);
            float hh = fmaxf(xh + rr * ah, 0.0f);
            hprev = z * hprev + (1.0f - z) * hh;
            hs[r_g * UU + c_g] = hprev;
            if (seqout)
                seqout[((size_t)(row0 + r_g) * TT + step) * UU + c_g] = hprev;
        }
        __syncthreads();
    }

    if (t < 256) {
        hfin1[(size_t)(row0 + r_g) * UU + c_g] = hprev;
        if (hfin2) hfin2[(size_t)(row0 + r_g) * UU + c_g] = hprev;
    }
}

// =====================================================================
// launch
// =====================================================================
extern "C" void kernel_launch(void* const* d_in, const int* in_sizes, int n_in,
                              void* d_out, int out_size)
{
    (void)in_sizes; (void)n_in; (void)out_size;
    const float* input = (const float*)d_in[0];  // [256,1024,64]
    const float* W1    = (const float*)d_in[1];  // [64,384]
    const float* U1    = (const float*)d_in[2];  // [128,384]
    const float* b1    = (const float*)d_in[3];  // [2,384]
    const float* W2    = (const float*)d_in[4];  // [128,384]
    const float* U2    = (const float*)d_in[5];  // [128,384]
    const float* b2    = (const float*)d_in[6];  // [2,384]
    float* out = (float*)d_out;                  // [3*256*128]: x | state1 | state2

    float *xw1, *seq1, *xw2;
    cudaGetSymbolAddress((void**)&xw1,  g_xw1);
    cudaGetSymbolAddress((void**)&seq1, g_seq1);
    cudaGetSymbolAddress((void**)&xw2,  g_xw2);

    // gemm smem: W(K*1536) + bias 1536 + max(xp ROWS*K*8, part 8*RPP*96*16)
    const int SMEM_G1 = 64 * 1536 + 1536 + (8 * 4 * 96 * 16);    // 98304+1536+49152 = 148992 (PASSES=2)
    const int SMEM_G2 = 128 * 1536 + 1536 + (8 * 2 * 96 * 16);   // 196608+1536+24576 = 222720 (PASSES=4)
    const int SMEM_S  = 73728 + 12288 + 1024;                    // 87040

    cudaFuncSetAttribute(gemm_kernel<8, 2>,  cudaFuncAttributeMaxDynamicSharedMemorySize, SMEM_G1);
    cudaFuncSetAttribute(gemm_kernel<16, 4>, cudaFuncAttributeMaxDynamicSharedMemorySize, SMEM_G2);
    cudaFuncSetAttribute(scan_kernel,        cudaFuncAttributeMaxDynamicSharedMemorySize, SMEM_S);

    const int nblk = (BB * TT) / 8;  // 32768 row-blocks of 8

    // Layer 1 input projection: xw1 = input @ W1 + b1[0]
    gemm_kernel<8, 2><<<148, 768, SMEM_G1>>>(input, W1, b1, xw1, nblk);
    // Layer 1 scan: seq1, state1
    scan_kernel<<<128, 384, SMEM_S>>>(xw1, U1, b1 + G3,
                                      seq1, out + 32768, nullptr);
    // Layer 2 input projection: xw2 = seq1 @ W2 + b2[0]
    gemm_kernel<16, 4><<<148, 768, SMEM_G2>>>(seq1, W2, b2, xw2, nblk);
    // Layer 2 scan: x (== state2)
    scan_kernel<<<128, 384, SMEM_S>>>(xw2, U2, b2 + G3,
                                      nullptr, out, out + 65536);
}

// round 16
// speedup vs baseline: 2.2514x; 1.0308x over previous
#include <cuda_runtime.h>

typedef unsigned long long ULL;

#define BB 256
#define TT 1024
#define FF 64
#define UU 128
#define G3 384   // 3*U

// ---------------- scratch buffers (no cudaMalloc allowed) ----------------
static __device__ float g_xw1[(size_t)BB * TT * G3];   // input proj layer1 [B,T,384]
static __device__ float g_seq1[(size_t)BB * TT * UU];  // layer1 hidden seq [B,T,128]
static __device__ float g_xw2[(size_t)BB * TT * G3];   // input proj layer2 [B,T,384]

// ---------------- helpers ----------------
__device__ __forceinline__ ULL fma2(ULL a, ULL b, ULL c) {
    ULL d;
    asm("fma.rn.f32x2 %0, %1, %2, %3;" : "=l"(d) : "l"(a), "l"(b), "l"(c));
    return d;
}
__device__ __forceinline__ ULL pack2(float lo, float hi) {
    ULL d;
    asm("mov.b64 %0, {%1, %2};" : "=l"(d) : "f"(lo), "f"(hi));
    return d;
}
__device__ __forceinline__ float4 add4(float4 a, float4 b) {
    return make_float4(a.x + b.x, a.y + b.y, a.z + b.z, a.w + b.w);
}
__device__ __forceinline__ float sigm(float x) {
    return 1.0f / (1.0f + __expf(-x));
}

// =====================================================================
// GEMM v5: out[M,384] = X[M,K] @ W[K,384] + bias,  K = 4*KC
// 384 threads, 16 rows/block, kg = t/96 (K/4 slice), cq = t%96.
// Per thread: first HST k's of its W slice HOISTED into registers
// (24 ULL), remaining SK k's streamed from smem. x staged packed (v,v),
// uniform LDS.128 (2 k / wavefront). Single-pass partial reduce,
// partial buffer overlaid on the dead xp region. 3 barriers / 16 rows.
// =====================================================================
template <int KC, int HST>
__global__ void __launch_bounds__(384, 1) gemm_kernel(
    const float* __restrict__ X, const float* __restrict__ W,
    const float* __restrict__ bias, float* __restrict__ out, int nblk)
{
    constexpr int K = 4 * KC;
    constexpr int SK = KC - HST;     // streamed k's per slice
    constexpr int ROWS = 16;

    extern __shared__ char smem[];
    ulonglong2* Wst   = (ulonglong2*)smem;                         // [SK][4][96]
    float4*     bias_s = (float4*)(smem + (size_t)SK * 6144);      // [96]
    // overlay region: xp [ROWS*K] ULL  then  part [4*ROWS][96] ull2
    ULL*        xp    = (ULL*)(smem + (size_t)SK * 6144 + 1536);
    ulonglong2* part  = (ulonglong2*)(smem + (size_t)SK * 6144 + 1536);
    const float4* partf = (const float4*)part;

    const int t  = threadIdx.x;
    const int cq = t % 96;
    const int kg = t / 96;           // 0..3
    const int kbase = kg * KC;

    // hoist W[k = kbase..kbase+HST-1][4cq..4cq+3] into registers
    ULL Wh[HST][2];
#pragma unroll
    for (int j = 0; j < HST; j++) {
        ulonglong2 uv = ((const ulonglong2*)(W + (size_t)(kbase + j) * G3))[cq];
        Wh[j][0] = uv.x; Wh[j][1] = uv.y;
    }
    // stage streamed W tail: k = kbase+HST .. kbase+KC-1
    for (int jj = 0; jj < SK; jj++) {
        Wst[(jj * 4 + kg) * 96 + cq] =
            ((const ulonglong2*)(W + (size_t)(kbase + HST + jj) * G3))[cq];
    }
    if (t < 96) bias_s[t] = ((const float4*)bias)[t];
    __syncthreads();

    const ulonglong2* WsP = Wst + kg * 96 + cq;   // stride 384 per streamed k

    for (int blk = blockIdx.x; blk < nblk; blk += gridDim.x) {
        const int row0 = blk * ROWS;
        // stage x packed (v,v), coalesced
        for (int i = t; i < ROWS * K; i += 384) {
            float v = X[(size_t)row0 * K + i];
            xp[i] = pack2(v, v);
        }
        __syncthreads();

        ULL acc[ROWS][2];
#pragma unroll
        for (int r = 0; r < ROWS; r++) { acc[r][0] = 0ull; acc[r][1] = 0ull; }

        // hoisted half
#pragma unroll
        for (int p = 0; p < HST / 2; p++) {
#pragma unroll
            for (int r = 0; r < ROWS; r++) {
                ulonglong2 xv = *(const ulonglong2*)&xp[r * K + kbase + 2 * p];
                acc[r][0] = fma2(Wh[2 * p][0],     xv.x, acc[r][0]);
                acc[r][1] = fma2(Wh[2 * p][1],     xv.x, acc[r][1]);
                acc[r][0] = fma2(Wh[2 * p + 1][0], xv.y, acc[r][0]);
                acc[r][1] = fma2(Wh[2 * p + 1][1], xv.y, acc[r][1]);
            }
        }
        // streamed half
#pragma unroll
        for (int p = 0; p < SK / 2; p++) {
            ulonglong2 u0 = WsP[(2 * p) * 384];
            ulonglong2 u1 = WsP[(2 * p + 1) * 384];
#pragma unroll
            for (int r = 0; r < ROWS; r++) {
                ulonglong2 xv = *(const ulonglong2*)&xp[r * K + kbase + HST + 2 * p];
                acc[r][0] = fma2(u0.x, xv.x, acc[r][0]);
                acc[r][1] = fma2(u0.y, xv.x, acc[r][1]);
                acc[r][0] = fma2(u1.x, xv.y, acc[r][0]);
                acc[r][1] = fma2(u1.y, xv.y, acc[r][1]);
            }
        }
        __syncthreads();   // all xp reads done before part STS overlays it

#pragma unroll
        for (int rr = 0; rr < ROWS; rr++)
            part[(kg * ROWS + rr) * 96 + cq] =
                make_ulonglong2(acc[rr][0], acc[rr][1]);
        __syncthreads();

        for (int slot = t; slot < ROWS * 96; slot += 384) {
            int rloc = slot / 96, cqq = slot % 96;
            float4 s = bias_s[cqq];
#pragma unroll
            for (int kg2 = 0; kg2 < 4; kg2++)
                s = add4(s, partf[(kg2 * ROWS + rloc) * 96 + cqq]);
            ((float4*)out)[(size_t)(row0 + rloc) * 96 + cqq] = s;
        }
        __syncthreads();
    }
}

// =====================================================================
// GRU scan v9 (unchanged from R15): hybrid register/smem U; h plain,
// loaded as uniform float4, duplicated to (h,h) on the ALU pipe.
// 128 CTAs x 2 rows, 384 threads.
// =====================================================================
#define HOIST 20
#define STRM  12

__global__ void __launch_bounds__(384, 1) scan_kernel(
    const float* __restrict__ xw,       // [B,T,384]
    const float* __restrict__ Urec,     // [128,384]
    const float* __restrict__ rbias,    // [384]
    float* __restrict__ seqout,         // [B,T,128] or null
    float* __restrict__ hfin1,          // [B,128]
    float* __restrict__ hfin2)          // optional second copy or null
{
    extern __shared__ char smem[];
    ulonglong2* Ust = (ulonglong2*)smem;                 // [STRM][4 kg][96 cq] 73728 B
    ulonglong2* part = (ulonglong2*)(smem + 73728);      // [4 kg][2 row][96]   12288 B
    const float* partF = (const float*)(smem + 73728);
    float*      hs   = (float*)(smem + 73728 + 12288);   // [2][128] plain       1024 B

    const int t    = threadIdx.x;
    const int cq   = t % 96;
    const int kg   = t / 96;            // 0..3
    const int kbase = kg * 32;
    const int row0 = blockIdx.x * 2;
    const int r_g = t >> 7;             // gate row (t<256)
    const int c_g = t & 127;            // gate column

    ULL Ureg[HOIST][2];
#pragma unroll
    for (int j = 0; j < HOIST; j++) {
        ulonglong2 uv = ((const ulonglong2*)(Urec + (size_t)(kbase + j) * G3))[cq];
        Ureg[j][0] = uv.x; Ureg[j][1] = uv.y;
    }
    for (int jj = 0; jj < STRM; jj++) {
        Ust[(jj * 4 + kg) * 96 + cq] =
            ((const ulonglong2*)(Urec + (size_t)(kbase + HOIST + jj) * G3))[cq];
    }

    float4 bq = ((const float4*)rbias)[cq];
    ULL b01 = (kg == 0) ? pack2(bq.x, bq.y) : 0ull;
    ULL b23 = (kg == 0) ? pack2(bq.z, bq.w) : 0ull;

    if (t < 256) hs[t] = 0.0f;
    float hprev = 0.0f;
    __syncthreads();

    const ulonglong2* UstP = Ust + kg * 96 + cq;   // stride 384 per streamed k
    const float* h0f = hs + kbase;                 // row0 slice (uniform)
    const float* h1f = hs + UU + kbase;            // row1 slice

    for (int step = 0; step < TT; ++step) {
        float xz = 0.f, xr = 0.f, xh = 0.f;
        if (t < 256) {
            const float* p = xw + ((size_t)(row0 + r_g) * TT + step) * G3 + c_g;
            xz = p[0]; xr = p[128]; xh = p[256];
        }

        ULL a00 = b01, a01 = b23;   // row0
        ULL a10 = b01, a11 = b23;   // row1

#pragma unroll
        for (int g = 0; g < HOIST / 4; g++) {
            float4 ha4 = *(const float4*)&h0f[4 * g];
            float4 hb4 = *(const float4*)&h1f[4 * g];
            ULL ha, hb;
            ha = pack2(ha4.x, ha4.x); hb = pack2(hb4.x, hb4.x);
            a00 = fma2(Ureg[4 * g][0], ha, a00);
            a01 = fma2(Ureg[4 * g][1], ha, a01);
            a10 = fma2(Ureg[4 * g][0], hb, a10);
            a11 = fma2(Ureg[4 * g][1], hb, a11);
            ha = pack2(ha4.y, ha4.y); hb = pack2(hb4.y, hb4.y);
            a00 = fma2(Ureg[4 * g + 1][0], ha, a00);
            a01 = fma2(Ureg[4 * g + 1][1], ha, a01);
            a10 = fma2(Ureg[4 * g + 1][0], hb, a10);
            a11 = fma2(Ureg[4 * g + 1][1], hb, a11);
            ha = pack2(ha4.z, ha4.z); hb = pack2(hb4.z, hb4.z);
            a00 = fma2(Ureg[4 * g + 2][0], ha, a00);
            a01 = fma2(Ureg[4 * g + 2][1], ha, a01);
            a10 = fma2(Ureg[4 * g + 2][0], hb, a10);
            a11 = fma2(Ureg[4 * g + 2][1], hb, a11);
            ha = pack2(ha4.w, ha4.w); hb = pack2(hb4.w, hb4.w);
            a00 = fma2(Ureg[4 * g + 3][0], ha, a00);
            a01 = fma2(Ureg[4 * g + 3][1], ha, a01);
            a10 = fma2(Ureg[4 * g + 3][0], hb, a10);
            a11 = fma2(Ureg[4 * g + 3][1], hb, a11);
        }
#pragma unroll
        for (int gg = 0; gg < STRM / 4; gg++) {
            float4 ha4 = *(const float4*)&h0f[HOIST + 4 * gg];
            float4 hb4 = *(const float4*)&h1f[HOIST + 4 * gg];
            ulonglong2 u0 = UstP[(4 * gg + 0) * 384];
            ulonglong2 u1 = UstP[(4 * gg + 1) * 384];
            ulonglong2 u2 = UstP[(4 * gg + 2) * 384];
            ulonglong2 u3 = UstP[(4 * gg + 3) * 384];
            ULL ha, hb;
            ha = pack2(ha4.x, ha4.x); hb = pack2(hb4.x, hb4.x);
            a00 = fma2(u0.x, ha, a00); a01 = fma2(u0.y, ha, a01);
            a10 = fma2(u0.x, hb, a10); a11 = fma2(u0.y, hb, a11);
            ha = pack2(ha4.y, ha4.y); hb = pack2(hb4.y, hb4.y);
            a00 = fma2(u1.x, ha, a00); a01 = fma2(u1.y, ha, a01);
            a10 = fma2(u1.x, hb, a10); a11 = fma2(u1.y, hb, a11);
            ha = pack2(ha4.z, ha4.z); hb = pack2(hb4.z, hb4.z);
            a00 = fma2(u2.x, ha, a00); a01 = fma2(u2.y, ha, a01);
            a10 = fma2(u2.x, hb, a10); a11 = fma2(u2.y, hb, a11);
            ha = pack2(ha4.w, ha4.w); hb = pack2(hb4.w, hb4.w);
            a00 = fma2(u3.x, ha, a00); a01 = fma2(u3.y, ha, a01);
            a10 = fma2(u3.x, hb, a10); a11 = fma2(u3.y, hb, a11);
        }
        part[(kg * 2 + 0) * 96 + cq] = make_ulonglong2(a00, a01);
        part[(kg * 2 + 1) * 96 + cq] = make_ulonglong2(a10, a11);
        __syncthreads();

        if (t < 256) {
            const float* pb = partF + r_g * 384 + c_g;
            float az = 0.f, ar = 0.f, ah = 0.f;
#pragma unroll
            for (int k2 = 0; k2 < 4; k2++) {
                const float* pk = pb + k2 * 768;
                az += pk[0];
                ar += pk[128];
                ah += pk[256];
            }
            float z  = sigm(xz + az);
            float rr = sigm(xr + ar);
            float hh = fmaxf(xh + rr * ah, 0.0f);
            hprev = z * hprev + (1.0f - z) * hh;
            hs[r_g * UU + c_g] = hprev;
            if (seqout)
                seqout[((size_t)(row0 + r_g) * TT + step) * UU + c_g] = hprev;
        }
        __syncthreads();
    }

    if (t < 256) {
        hfin1[(size_t)(row0 + r_g) * UU + c_g] = hprev;
        if (hfin2) hfin2[(size_t)(row0 + r_g) * UU + c_g] = hprev;
    }
}

// =====================================================================
// launch
// =====================================================================
extern "C" void kernel_launch(void* const* d_in, const int* in_sizes, int n_in,
                              void* d_out, int out_size)
{
    (void)in_sizes; (void)n_in; (void)out_size;
    const float* input = (const float*)d_in[0];  // [256,1024,64]
    const float* W1    = (const float*)d_in[1];  // [64,384]
    const float* U1    = (const float*)d_in[2];  // [128,384]
    const float* b1    = (const float*)d_in[3];  // [2,384]
    const float* W2    = (const float*)d_in[4];  // [128,384]
    const float* U2    = (const float*)d_in[5];  // [128,384]
    const float* b2    = (const float*)d_in[6];  // [2,384]
    float* out = (float*)d_out;                  // [3*256*128]: x | state1 | state2

    float *xw1, *seq1, *xw2;
    cudaGetSymbolAddress((void**)&xw1,  g_xw1);
    cudaGetSymbolAddress((void**)&seq1, g_seq1);
    cudaGetSymbolAddress((void**)&xw2,  g_xw2);

    // gemm smem: Wst(SK*6144) + bias 1536 + part 4*16*96*16 (= 98304, covers xp)
    const int SMEM_G1 = 4 * 6144 + 1536 + 98304;     // K=64,  HST=12, SK=4  -> 124416
    const int SMEM_G2 = 20 * 6144 + 1536 + 98304;    // K=128, HST=12, SK=20 -> 222720
    const int SMEM_S  = 73728 + 12288 + 1024;        // 87040

    cudaFuncSetAttribute(gemm_kernel<16, 12>, cudaFuncAttributeMaxDynamicSharedMemorySize, SMEM_G1);
    cudaFuncSetAttribute(gemm_kernel<32, 12>, cudaFuncAttributeMaxDynamicSharedMemorySize, SMEM_G2);
    cudaFuncSetAttribute(scan_kernel,         cudaFuncAttributeMaxDynamicSharedMemorySize, SMEM_S);

    const int nblk = (BB * TT) / 16;  // 16384 row-blocks of 16

    // Layer 1 input projection: xw1 = input @ W1 + b1[0]
    gemm_kernel<16, 12><<<148, 384, SMEM_G1>>>(input, W1, b1, xw1, nblk);
    // Layer 1 scan: seq1, state1
    scan_kernel<<<128, 384, SMEM_S>>>(xw1, U1, b1 + G3,
                                      seq1, out + 32768, nullptr);
    // Layer 2 input projection: xw2 = seq1 @ W2 + b2[0]
    gemm_kernel<32, 12><<<148, 384, SMEM_G2>>>(seq1, W2, b2, xw2, nblk);
    // Layer 2 scan: x (== state2)
    scan_kernel<<<128, 384, SMEM_S>>>(xw2, U2, b2 + G3,
                                      nullptr, out, out + 65536);
}